// round 3
// baseline (speedup 1.0000x reference)
#include <cuda_runtime.h>
#include <math.h>
#include <stdint.h>

#define B_ 16
#define L_ 1024
#define STATE_DIM 17
#define D_MODEL 512
#define D_STATE 128
#define D_CONV 4
#define N_LAYERS 6
#define HEADDIM 64
#define D_INNER 1024
#define NHEADS 16
#define CONV_DIM 1280          // D_INNER + 2*D_STATE
#define D_IN_PROJ 2320         // 2*D_INNER + 2*D_STATE + NHEADS
#define NTOK (B_*L_)

// ---------------- scratch (allocation-free: __device__ globals) -------------
__device__ float g_x[NTOK * D_MODEL];        // residual stream
__device__ float g_h[NTOK * D_MODEL];        // layernorm output
__device__ float g_zx[NTOK * D_IN_PROJ];     // in_proj output
__device__ float g_xbc[NTOK * CONV_DIM];     // conv+silu output
__device__ float g_dt[NTOK * NHEADS];        // softplus(dt + bias)
__device__ float g_y[NTOK * D_INNER];        // scan output / gated+rms output

// ---------------- input projection + RoPE ----------------------------------
__global__ void input_rope_kernel(const float* __restrict__ states,
                                  const float* __restrict__ W,
                                  const float* __restrict__ bias,
                                  float* __restrict__ out) {
    int tok = blockIdx.x;
    int l = tok % L_;
    __shared__ float s[STATE_DIM];
    int t = threadIdx.x;  // 256 threads = 256 rope pairs
    if (t < STATE_DIM) s[t] = states[tok * STATE_DIM + t];
    __syncthreads();
    float x1 = bias[2 * t], x2 = bias[2 * t + 1];
#pragma unroll
    for (int k = 0; k < STATE_DIM; k++) {
        float sv = s[k];
        x1 += sv * W[k * D_MODEL + 2 * t];
        x2 += sv * W[k * D_MODEL + 2 * t + 1];
    }
    float inv = expf(-((2.0f * t) / (float)D_MODEL) * logf(10000.0f));
    float fr = (float)l * inv;
    float c = cosf(fr), sn = sinf(fr);
    out[tok * D_MODEL + 2 * t]     = x1 * c - x2 * sn;
    out[tok * D_MODEL + 2 * t + 1] = x1 * sn + x2 * c;
}

// ---------------- layernorm (D_MODEL=512) -----------------------------------
__global__ void layernorm_kernel(const float* __restrict__ x,
                                 const float* __restrict__ g,
                                 const float* __restrict__ b,
                                 float* __restrict__ out) {
    int tok = blockIdx.x;
    int t = threadIdx.x;  // 256
    float v0 = x[tok * D_MODEL + t];
    float v1 = x[tok * D_MODEL + 256 + t];
    __shared__ float red[256];
    red[t] = v0 + v1;
    __syncthreads();
#pragma unroll
    for (int s = 128; s > 0; s >>= 1) {
        if (t < s) red[t] += red[t + s];
        __syncthreads();
    }
    float mu = red[0] * (1.0f / D_MODEL);
    __syncthreads();
    float c0 = v0 - mu, c1 = v1 - mu;
    red[t] = c0 * c0 + c1 * c1;
    __syncthreads();
#pragma unroll
    for (int s = 128; s > 0; s >>= 1) {
        if (t < s) red[t] += red[t + s];
        __syncthreads();
    }
    float inv = rsqrtf(red[0] * (1.0f / D_MODEL) + 1e-5f);
    out[tok * D_MODEL + t]       = c0 * inv * g[t] + b[t];
    out[tok * D_MODEL + 256 + t] = c1 * inv * g[256 + t] + b[256 + t];
}

// ---------------- generic SGEMM: C = A(MxK) @ B(KxN) [+bias] [+res] --------
// BM=BN=128, BK=8, 256 threads, 8x8 per thread.
#define BM 128
#define BN 128
#define BK 8
__global__ __launch_bounds__(256) void sgemm_kernel(
    const float* __restrict__ A, const float* __restrict__ Bm,
    const float* __restrict__ bias, const float* __restrict__ res,
    float* __restrict__ C, int M, int N, int K) {
    __shared__ float As[BK][BM];
    __shared__ float Bs[BK][BN];
    int bcol = blockIdx.x, brow = blockIdx.y;
    int tid = threadIdx.x;
    int trow = (tid / 16) * 8;
    int tcol = (tid % 16) * 8;
    int aRow = tid / 2;
    int aCol = (tid % 2) * 4;
    int bRow = tid / 32;
    int bColL = (tid % 32) * 4;

    float acc[8][8];
#pragma unroll
    for (int i = 0; i < 8; i++)
#pragma unroll
        for (int j = 0; j < 8; j++) acc[i][j] = 0.0f;

    const float* Ap = A + (size_t)(brow * BM) * K;
    for (int k0 = 0; k0 < K; k0 += BK) {
        // load A tile (M multiple of 128, K multiple of 8 -> no bounds needed)
        float4 a4 = *(const float4*)(Ap + (size_t)aRow * K + k0 + aCol);
        As[aCol + 0][aRow] = a4.x;
        As[aCol + 1][aRow] = a4.y;
        As[aCol + 2][aRow] = a4.z;
        As[aCol + 3][aRow] = a4.w;
        // load B tile with N bounds check
        int gcol = bcol * BN + bColL;
        float4 b4;
        if (gcol + 3 < N) {
            b4 = *(const float4*)(Bm + (size_t)(k0 + bRow) * N + gcol);
        } else {
            b4.x = (gcol + 0 < N) ? Bm[(size_t)(k0 + bRow) * N + gcol + 0] : 0.0f;
            b4.y = (gcol + 1 < N) ? Bm[(size_t)(k0 + bRow) * N + gcol + 1] : 0.0f;
            b4.z = (gcol + 2 < N) ? Bm[(size_t)(k0 + bRow) * N + gcol + 2] : 0.0f;
            b4.w = (gcol + 3 < N) ? Bm[(size_t)(k0 + bRow) * N + gcol + 3] : 0.0f;
        }
        *(float4*)&Bs[bRow][bColL] = b4;
        __syncthreads();
#pragma unroll
        for (int kk = 0; kk < BK; kk++) {
            float4 ar0 = *(const float4*)&As[kk][trow];
            float4 ar1 = *(const float4*)&As[kk][trow + 4];
            float4 br0 = *(const float4*)&Bs[kk][tcol];
            float4 br1 = *(const float4*)&Bs[kk][tcol + 4];
            float ar[8] = {ar0.x, ar0.y, ar0.z, ar0.w, ar1.x, ar1.y, ar1.z, ar1.w};
            float br[8] = {br0.x, br0.y, br0.z, br0.w, br1.x, br1.y, br1.z, br1.w};
#pragma unroll
            for (int i = 0; i < 8; i++)
#pragma unroll
                for (int j = 0; j < 8; j++) acc[i][j] += ar[i] * br[j];
        }
        __syncthreads();
    }
#pragma unroll
    for (int i = 0; i < 8; i++) {
        int grow = brow * BM + trow + i;
#pragma unroll
        for (int j = 0; j < 8; j++) {
            int gcol = bcol * BN + tcol + j;
            if (gcol < N) {
                float v = acc[i][j];
                if (bias) v += bias[gcol];
                if (res) v += res[(size_t)grow * N + gcol];
                C[(size_t)grow * N + gcol] = v;
            }
        }
    }
}

// ---------------- causal conv1d (K=4, depthwise) + SiLU ---------------------
__global__ void conv_silu_kernel(const float* __restrict__ zx,
                                 const float* __restrict__ cw,
                                 const float* __restrict__ cb,
                                 float* __restrict__ xbc) {
    int tok = blockIdx.x;
    int b = tok / L_;
    int l = tok % L_;
    for (int c = threadIdx.x; c < CONV_DIM; c += 256) {
        float acc = cb[c];
        float w0 = cw[c * D_CONV + 0], w1 = cw[c * D_CONV + 1];
        float w2 = cw[c * D_CONV + 2], w3 = cw[c * D_CONV + 3];
        const float* base = zx + (size_t)(b * L_) * D_IN_PROJ + D_INNER + c;
        if (l >= 3) acc += base[(size_t)(l - 3) * D_IN_PROJ] * w0;
        if (l >= 2) acc += base[(size_t)(l - 2) * D_IN_PROJ] * w1;
        if (l >= 1) acc += base[(size_t)(l - 1) * D_IN_PROJ] * w2;
        acc += base[(size_t)l * D_IN_PROJ] * w3;
        xbc[(size_t)tok * CONV_DIM + c] = acc / (1.0f + expf(-acc));
    }
}

// ---------------- dt = softplus(dt_raw + bias) ------------------------------
__global__ void dt_kernel(const float* __restrict__ zx,
                          const float* __restrict__ dt_bias,
                          float* __restrict__ dto) {
    int i = blockIdx.x * blockDim.x + threadIdx.x;
    if (i >= NTOK * NHEADS) return;
    int h = i % NHEADS;
    int tok = i / NHEADS;
    float v = zx[(size_t)tok * D_IN_PROJ + D_INNER + CONV_DIM + h] + dt_bias[h];
    dto[i] = (v > 20.0f) ? v : log1pf(expf(v));
}

// ---------------- selective scan (sequential over L) ------------------------
// grid = (NHEADS, B_), block = 256. Thread t: p = t>>2 (head dim), q = t&3.
// Each thread owns 32 state elements n = q + 4*j (conflict-free smem).
__global__ __launch_bounds__(256) void scan_kernel(
    const float* __restrict__ xbc, const float* __restrict__ dt,
    const float* __restrict__ A_log, const float* __restrict__ Dp,
    float* __restrict__ y) {
    int h = blockIdx.x, b = blockIdx.y;
    int t = threadIdx.x;
    int p = t >> 2;
    int q = t & 3;
    __shared__ float sB[2][D_STATE], sC[2][D_STATE], sX[2][HEADDIM];
    __shared__ float sDec[2], sDtt[2];
    float A = -expf(A_log[h]);
    float Dh = Dp[h];
    float s[32];
#pragma unroll
    for (int j = 0; j < 32; j++) s[j] = 0.0f;

    // preload l = 0
    {
        const float* base = xbc + (size_t)(b * L_) * CONV_DIM;
        if (t < 128) {
            sB[0][t] = base[D_INNER + t];
            sC[0][t] = base[D_INNER + D_STATE + t];
        } else if (t < 192) {
            sX[0][t - 128] = base[h * HEADDIM + (t - 128)];
        } else if (t == 255) {
            float d = dt[(size_t)(b * L_) * NHEADS + h];
            sDtt[0] = d;
            sDec[0] = expf(d * A);
        }
    }
    __syncthreads();

    for (int l = 0; l < L_; l++) {
        int cur = l & 1, nxt = cur ^ 1;
        if (l + 1 < L_) {
            const float* base = xbc + (size_t)(b * L_ + l + 1) * CONV_DIM;
            if (t < 128) {
                sB[nxt][t] = base[D_INNER + t];
                sC[nxt][t] = base[D_INNER + D_STATE + t];
            } else if (t < 192) {
                sX[nxt][t - 128] = base[h * HEADDIM + (t - 128)];
            } else if (t == 255) {
                float d = dt[(size_t)(b * L_ + l + 1) * NHEADS + h];
                sDtt[nxt] = d;
                sDec[nxt] = expf(d * A);
            }
        }
        float xp = sX[cur][p];
        float dtx = sDtt[cur] * xp;
        float dec = sDec[cur];
        float acc = 0.0f;
#pragma unroll
        for (int j = 0; j < 32; j++) {
            int n = q + 4 * j;
            float bn = sB[cur][n];
            float cn = sC[cur][n];
            s[j] = s[j] * dec + dtx * bn;
            acc += s[j] * cn;
        }
        acc += __shfl_xor_sync(0xffffffffu, acc, 1);
        acc += __shfl_xor_sync(0xffffffffu, acc, 2);
        if (q == 0)
            y[(size_t)(b * L_ + l) * D_INNER + h * HEADDIM + p] = acc + Dh * xp;
        __syncthreads();
    }
}

// ---------------- gate (y * silu(z)) + RMSNorm ------------------------------
__global__ void gate_rms_kernel(const float* __restrict__ zx,
                                const float* __restrict__ rms_w,
                                float* __restrict__ y) {
    int tok = blockIdx.x;
    int t = threadIdx.x;  // 256, 4 elems each
    float v[4];
    float ss = 0.0f;
#pragma unroll
    for (int j = 0; j < 4; j++) {
        int c = t + j * 256;
        float z = zx[(size_t)tok * D_IN_PROJ + c];
        float yy = y[(size_t)tok * D_INNER + c];
        float g = z / (1.0f + expf(-z));
        v[j] = yy * g;
        ss += v[j] * v[j];
    }
    __shared__ float red[256];
    red[t] = ss;
    __syncthreads();
#pragma unroll
    for (int s = 128; s > 0; s >>= 1) {
        if (t < s) red[t] += red[t + s];
        __syncthreads();
    }
    float inv = rsqrtf(red[0] * (1.0f / D_INNER) + 1e-5f);
#pragma unroll
    for (int j = 0; j < 4; j++) {
        int c = t + j * 256;
        y[(size_t)tok * D_INNER + c] = v[j] * inv * rms_w[c];
    }
}

// ---------------- launch -----------------------------------------------------
extern "C" void kernel_launch(void* const* d_in, const int* in_sizes, int n_in,
                              void* d_out, int out_size) {
    const float* states        = (const float*)d_in[0];
    const float* input_proj_w  = (const float*)d_in[1];
    const float* input_proj_b  = (const float*)d_in[2];
    const float* ln_g          = (const float*)d_in[3];
    const float* ln_b          = (const float*)d_in[4];
    const float* in_proj_w     = (const float*)d_in[5];
    const float* conv_w        = (const float*)d_in[6];
    const float* conv_b        = (const float*)d_in[7];
    const float* dt_bias       = (const float*)d_in[8];
    const float* A_log         = (const float*)d_in[9];
    const float* D_param       = (const float*)d_in[10];
    const float* rms_w         = (const float*)d_in[11];
    const float* out_proj_w    = (const float*)d_in[12];
    const float* post_ln_g     = (const float*)d_in[13];
    const float* post_ln_b     = (const float*)d_in[14];
    const float* output_proj_w = (const float*)d_in[15];
    const float* output_proj_b = (const float*)d_in[16];

    float *px, *ph, *pzx, *pxbc, *pdt, *py;
    cudaGetSymbolAddress((void**)&px, g_x);
    cudaGetSymbolAddress((void**)&ph, g_h);
    cudaGetSymbolAddress((void**)&pzx, g_zx);
    cudaGetSymbolAddress((void**)&pxbc, g_xbc);
    cudaGetSymbolAddress((void**)&pdt, g_dt);
    cudaGetSymbolAddress((void**)&py, g_y);

    input_rope_kernel<<<NTOK, 256>>>(states, input_proj_w, input_proj_b, px);

    for (int l = 0; l < N_LAYERS; l++) {
        layernorm_kernel<<<NTOK, 256>>>(px, ln_g + l * D_MODEL, ln_b + l * D_MODEL, ph);

        dim3 g1((D_IN_PROJ + BN - 1) / BN, NTOK / BM);
        sgemm_kernel<<<g1, 256>>>(ph, in_proj_w + (size_t)l * D_MODEL * D_IN_PROJ,
                                  nullptr, nullptr, pzx, NTOK, D_IN_PROJ, D_MODEL);

        conv_silu_kernel<<<NTOK, 256>>>(pzx, conv_w + (size_t)l * CONV_DIM * D_CONV,
                                        conv_b + (size_t)l * CONV_DIM, pxbc);
        dt_kernel<<<(NTOK * NHEADS + 255) / 256, 256>>>(pzx, dt_bias + l * NHEADS, pdt);

        scan_kernel<<<dim3(NHEADS, B_), 256>>>(pxbc, pdt, A_log + l * NHEADS,
                                               D_param + l * NHEADS, py);

        gate_rms_kernel<<<NTOK, 256>>>(pzx, rms_w + (size_t)l * D_INNER, py);

        dim3 g2((D_MODEL + BN - 1) / BN, NTOK / BM);
        sgemm_kernel<<<g2, 256>>>(py, out_proj_w + (size_t)l * D_INNER * D_MODEL,
                                  nullptr, px, px, NTOK, D_MODEL, D_INNER);
    }

    layernorm_kernel<<<NTOK, 256>>>(px, post_ln_g, post_ln_b, ph);
    dim3 g3((D_MODEL + BN - 1) / BN, NTOK / BM);
    sgemm_kernel<<<g3, 256>>>(ph, output_proj_w, output_proj_b, nullptr,
                              (float*)d_out, NTOK, D_MODEL, D_MODEL);
}

// round 6
// speedup vs baseline: 1.0123x; 1.0123x over previous
#include <cuda_runtime.h>
#include <math.h>
#include <stdint.h>

#define B_ 16
#define L_ 1024
#define STATE_DIM 17
#define D_MODEL 512
#define D_STATE 128
#define D_CONV 4
#define N_LAYERS 6
#define HEADDIM 64
#define D_INNER 1024
#define NHEADS 16
#define CONV_DIM 1280          // D_INNER + 2*D_STATE
#define D_IN_PROJ 2320         // 2*D_INNER + 2*D_STATE + NHEADS
#define NTOK (B_*L_)

// ---------------- scratch (allocation-free: __device__ globals) -------------
__device__ float g_x[NTOK * D_MODEL];        // residual stream
__device__ float g_h[NTOK * D_MODEL];        // layernorm output
__device__ float g_zx[NTOK * D_IN_PROJ];     // in_proj output
__device__ float g_xbc[NTOK * CONV_DIM];     // conv+silu output
__device__ float g_dt[NTOK * NHEADS];        // softplus(dt + bias)
__device__ float g_y[NTOK * D_INNER];        // scan output / gated+rms output

// ---------------- input projection + RoPE ----------------------------------
__global__ void input_rope_kernel(const float* __restrict__ states,
                                  const float* __restrict__ W,
                                  const float* __restrict__ bias,
                                  float* __restrict__ out) {
    int tok = blockIdx.x;
    int l = tok % L_;
    __shared__ float s[STATE_DIM];
    int t = threadIdx.x;  // 256 threads = 256 rope pairs
    if (t < STATE_DIM) s[t] = states[tok * STATE_DIM + t];
    __syncthreads();
    float x1 = bias[2 * t], x2 = bias[2 * t + 1];
#pragma unroll
    for (int k = 0; k < STATE_DIM; k++) {
        float sv = s[k];
        x1 += sv * W[k * D_MODEL + 2 * t];
        x2 += sv * W[k * D_MODEL + 2 * t + 1];
    }
    float inv = expf(-((2.0f * t) / (float)D_MODEL) * logf(10000.0f));
    float fr = (float)l * inv;
    float c = cosf(fr), sn = sinf(fr);
    out[tok * D_MODEL + 2 * t]     = x1 * c - x2 * sn;
    out[tok * D_MODEL + 2 * t + 1] = x1 * sn + x2 * c;
}

// ---------------- layernorm (D_MODEL=512) -----------------------------------
__global__ void layernorm_kernel(const float* __restrict__ x,
                                 const float* __restrict__ g,
                                 const float* __restrict__ b,
                                 float* __restrict__ out) {
    int tok = blockIdx.x;
    int t = threadIdx.x;  // 256
    float v0 = x[tok * D_MODEL + t];
    float v1 = x[tok * D_MODEL + 256 + t];
    __shared__ float red[256];
    red[t] = v0 + v1;
    __syncthreads();
#pragma unroll
    for (int s = 128; s > 0; s >>= 1) {
        if (t < s) red[t] += red[t + s];
        __syncthreads();
    }
    float mu = red[0] * (1.0f / D_MODEL);
    __syncthreads();
    float c0 = v0 - mu, c1 = v1 - mu;
    red[t] = c0 * c0 + c1 * c1;
    __syncthreads();
#pragma unroll
    for (int s = 128; s > 0; s >>= 1) {
        if (t < s) red[t] += red[t + s];
        __syncthreads();
    }
    float inv = rsqrtf(red[0] * (1.0f / D_MODEL) + 1e-5f);
    out[tok * D_MODEL + t]       = c0 * inv * g[t] + b[t];
    out[tok * D_MODEL + 256 + t] = c1 * inv * g[256 + t] + b[256 + t];
}

// ---------------- 3xTF32 tensor-core GEMM -----------------------------------
// C[M,N] = A[M,K] @ B[K,N] (+bias) (+res), fp32-class accuracy via
// hi/lo tf32 decomposition: a*b ~= ah*bh + ah*bl + al*bh (fp32 accum).
// BM=BN=128, BK=16, 256 thr = 8 warps (2x4), warp tile 64x32,
// mma.m16n8k8 frags 4x4. Requires M%128==0, K%16==0; N even.
#define BM 128
#define BN 128
#define BK 16
#define APAD 20   // words per A row -> conflict-free frag loads
#define BPAD 136  // words per B row -> conflict-free frag loads

__device__ __forceinline__ uint32_t f2tf(float x) {
    uint32_t u;
    asm("cvt.rna.tf32.f32 %0, %1;" : "=r"(u) : "f"(x));
    return u;
}

// hi = tf32(x), lo = tf32(x - hi)
__device__ __forceinline__ void split_tf32(float x, uint32_t& hi, uint32_t& lo) {
    hi = f2tf(x);
    float hf = __uint_as_float(hi);
    lo = f2tf(x - hf);
}

__device__ __forceinline__ void mma_tf32(float* c, const uint32_t* a,
                                         const uint32_t* b) {
    asm volatile(
        "mma.sync.aligned.m16n8k8.row.col.f32.tf32.tf32.f32 "
        "{%0,%1,%2,%3}, {%4,%5,%6,%7}, {%8,%9}, {%0,%1,%2,%3};\n"
        : "+f"(c[0]), "+f"(c[1]), "+f"(c[2]), "+f"(c[3])
        : "r"(a[0]), "r"(a[1]), "r"(a[2]), "r"(a[3]), "r"(b[0]), "r"(b[1]));
}

__global__ __launch_bounds__(256) void tf32_gemm_kernel(
    const float* __restrict__ A, const float* __restrict__ Bm,
    const float* __restrict__ bias, const float* __restrict__ res,
    float* __restrict__ C, int M, int N, int K) {
    __shared__ uint32_t AsH[BM * APAD];
    __shared__ uint32_t AsL[BM * APAD];
    __shared__ uint32_t BsH[BK * BPAD];
    __shared__ uint32_t BsL[BK * BPAD];

    int tid = threadIdx.x;
    int bcol = blockIdx.x, brow = blockIdx.y;
    int warp = tid >> 5, lane = tid & 31;
    int grp = lane >> 2, qid = lane & 3;
    int wm = (warp >> 2) * 64;   // warp row offset in tile
    int wn = (warp & 3) * 32;    // warp col offset in tile

    // fill-path indices
    int aRow = tid >> 1;               // 0..127
    int aCol = (tid & 1) * 8;          // 0 or 8
    int bRow = tid >> 4;               // 0..15
    int bCol = (tid & 15) * 8;         // 0..120

    float acc[4][4][4];
#pragma unroll
    for (int i = 0; i < 4; i++)
#pragma unroll
        for (int j = 0; j < 4; j++)
#pragma unroll
            for (int r = 0; r < 4; r++) acc[i][j][r] = 0.0f;

    const float* Ap = A + (size_t)(brow * BM + aRow) * K + aCol;
    int gcolB = bcol * BN + bCol;

    for (int k0 = 0; k0 < K; k0 += BK) {
        // ---- A tile: 128x16, vector load + hi/lo split ----
        float4 a0 = *(const float4*)(Ap + k0);
        float4 a1 = *(const float4*)(Ap + k0 + 4);
        uint4 h0, l0, h1, l1;
        split_tf32(a0.x, h0.x, l0.x); split_tf32(a0.y, h0.y, l0.y);
        split_tf32(a0.z, h0.z, l0.z); split_tf32(a0.w, h0.w, l0.w);
        split_tf32(a1.x, h1.x, l1.x); split_tf32(a1.y, h1.y, l1.y);
        split_tf32(a1.z, h1.z, l1.z); split_tf32(a1.w, h1.w, l1.w);
        *(uint4*)&AsH[aRow * APAD + aCol]     = h0;
        *(uint4*)&AsH[aRow * APAD + aCol + 4] = h1;
        *(uint4*)&AsL[aRow * APAD + aCol]     = l0;
        *(uint4*)&AsL[aRow * APAD + aCol + 4] = l1;
        // ---- B tile: 16x128 with N bounds ----
        const float* Bp = Bm + (size_t)(k0 + bRow) * N;
        float bv[8];
        if (gcolB + 7 < N) {
            float4 b0 = *(const float4*)(Bp + gcolB);
            float4 b1 = *(const float4*)(Bp + gcolB + 4);
            bv[0] = b0.x; bv[1] = b0.y; bv[2] = b0.z; bv[3] = b0.w;
            bv[4] = b1.x; bv[5] = b1.y; bv[6] = b1.z; bv[7] = b1.w;
        } else {
#pragma unroll
            for (int j = 0; j < 8; j++)
                bv[j] = (gcolB + j < N) ? Bp[gcolB + j] : 0.0f;
        }
        uint4 bh0, bl0, bh1, bl1;
        split_tf32(bv[0], bh0.x, bl0.x); split_tf32(bv[1], bh0.y, bl0.y);
        split_tf32(bv[2], bh0.z, bl0.z); split_tf32(bv[3], bh0.w, bl0.w);
        split_tf32(bv[4], bh1.x, bl1.x); split_tf32(bv[5], bh1.y, bl1.y);
        split_tf32(bv[6], bh1.z, bl1.z); split_tf32(bv[7], bh1.w, bl1.w);
        *(uint4*)&BsH[bRow * BPAD + bCol]     = bh0;
        *(uint4*)&BsH[bRow * BPAD + bCol + 4] = bh1;
        *(uint4*)&BsL[bRow * BPAD + bCol]     = bl0;
        *(uint4*)&BsL[bRow * BPAD + bCol + 4] = bl1;
        __syncthreads();

#pragma unroll
        for (int ks = 0; ks < BK; ks += 8) {
            uint32_t afH[4][4], afL[4][4];
#pragma unroll
            for (int mi = 0; mi < 4; mi++) {
                int r0 = wm + mi * 16 + grp;
                int i0 = r0 * APAD + ks + qid;
                int i1 = (r0 + 8) * APAD + ks + qid;
                afH[mi][0] = AsH[i0];     afH[mi][1] = AsH[i1];
                afH[mi][2] = AsH[i0 + 4]; afH[mi][3] = AsH[i1 + 4];
                afL[mi][0] = AsL[i0];     afL[mi][1] = AsL[i1];
                afL[mi][2] = AsL[i0 + 4]; afL[mi][3] = AsL[i1 + 4];
            }
            uint32_t bfH[4][2], bfL[4][2];
#pragma unroll
            for (int ni = 0; ni < 4; ni++) {
                int cc = wn + ni * 8 + grp;
                bfH[ni][0] = BsH[(ks + qid) * BPAD + cc];
                bfH[ni][1] = BsH[(ks + qid + 4) * BPAD + cc];
                bfL[ni][0] = BsL[(ks + qid) * BPAD + cc];
                bfL[ni][1] = BsL[(ks + qid + 4) * BPAD + cc];
            }
#pragma unroll
            for (int mi = 0; mi < 4; mi++)
#pragma unroll
                for (int ni = 0; ni < 4; ni++) {
                    mma_tf32(acc[mi][ni], afH[mi], bfL[ni]);  // hi*lo
                    mma_tf32(acc[mi][ni], afL[mi], bfH[ni]);  // lo*hi
                    mma_tf32(acc[mi][ni], afH[mi], bfH[ni]);  // hi*hi
                }
        }
        __syncthreads();
    }

    // ---- epilogue ----
#pragma unroll
    for (int mi = 0; mi < 4; mi++) {
#pragma unroll
        for (int half = 0; half < 2; half++) {
            int grow = brow * BM + wm + mi * 16 + grp + half * 8;
#pragma unroll
            for (int ni = 0; ni < 4; ni++) {
                int gcol = bcol * BN + wn + ni * 8 + qid * 2;
                if (gcol < N) {   // N even, pair stays in-bounds together
                    float v0 = acc[mi][ni][half * 2 + 0];
                    float v1 = acc[mi][ni][half * 2 + 1];
                    if (bias) { v0 += bias[gcol]; v1 += bias[gcol + 1]; }
                    if (res) {
                        const float* rp = res + (size_t)grow * N + gcol;
                        v0 += rp[0]; v1 += rp[1];
                    }
                    float2* cp = (float2*)(C + (size_t)grow * N + gcol);
                    *cp = make_float2(v0, v1);
                }
            }
        }
    }
}

// ---------------- causal conv1d (K=4, depthwise) + SiLU ---------------------
__global__ void conv_silu_kernel(const float* __restrict__ zx,
                                 const float* __restrict__ cw,
                                 const float* __restrict__ cb,
                                 float* __restrict__ xbc) {
    int tok = blockIdx.x;
    int b = tok / L_;
    int l = tok % L_;
    for (int c = threadIdx.x; c < CONV_DIM; c += 256) {
        float acc = cb[c];
        float w0 = cw[c * D_CONV + 0], w1 = cw[c * D_CONV + 1];
        float w2 = cw[c * D_CONV + 2], w3 = cw[c * D_CONV + 3];
        const float* base = zx + (size_t)(b * L_) * D_IN_PROJ + D_INNER + c;
        if (l >= 3) acc += base[(size_t)(l - 3) * D_IN_PROJ] * w0;
        if (l >= 2) acc += base[(size_t)(l - 2) * D_IN_PROJ] * w1;
        if (l >= 1) acc += base[(size_t)(l - 1) * D_IN_PROJ] * w2;
        acc += base[(size_t)l * D_IN_PROJ] * w3;
        xbc[(size_t)tok * CONV_DIM + c] = acc / (1.0f + expf(-acc));
    }
}

// ---------------- dt = softplus(dt_raw + bias) ------------------------------
__global__ void dt_kernel(const float* __restrict__ zx,
                          const float* __restrict__ dt_bias,
                          float* __restrict__ dto) {
    int i = blockIdx.x * blockDim.x + threadIdx.x;
    if (i >= NTOK * NHEADS) return;
    int h = i % NHEADS;
    int tok = i / NHEADS;
    float v = zx[(size_t)tok * D_IN_PROJ + D_INNER + CONV_DIM + h] + dt_bias[h];
    dto[i] = (v > 20.0f) ? v : log1pf(expf(v));
}

// ---------------- selective scan (sequential over L) ------------------------
__global__ __launch_bounds__(256) void scan_kernel(
    const float* __restrict__ xbc, const float* __restrict__ dt,
    const float* __restrict__ A_log, const float* __restrict__ Dp,
    float* __restrict__ y) {
    int h = blockIdx.x, b = blockIdx.y;
    int t = threadIdx.x;
    int p = t >> 2;
    int q = t & 3;
    __shared__ float sB[2][D_STATE], sC[2][D_STATE], sX[2][HEADDIM];
    __shared__ float sDec[2], sDtt[2];
    float A = -expf(A_log[h]);
    float Dh = Dp[h];
    float s[32];
#pragma unroll
    for (int j = 0; j < 32; j++) s[j] = 0.0f;

    {
        const float* base = xbc + (size_t)(b * L_) * CONV_DIM;
        if (t < 128) {
            sB[0][t] = base[D_INNER + t];
            sC[0][t] = base[D_INNER + D_STATE + t];
        } else if (t < 192) {
            sX[0][t - 128] = base[h * HEADDIM + (t - 128)];
        } else if (t == 255) {
            float d = dt[(size_t)(b * L_) * NHEADS + h];
            sDtt[0] = d;
            sDec[0] = expf(d * A);
        }
    }
    __syncthreads();

    for (int l = 0; l < L_; l++) {
        int cur = l & 1, nxt = cur ^ 1;
        if (l + 1 < L_) {
            const float* base = xbc + (size_t)(b * L_ + l + 1) * CONV_DIM;
            if (t < 128) {
                sB[nxt][t] = base[D_INNER + t];
                sC[nxt][t] = base[D_INNER + D_STATE + t];
            } else if (t < 192) {
                sX[nxt][t - 128] = base[h * HEADDIM + (t - 128)];
            } else if (t == 255) {
                float d = dt[(size_t)(b * L_ + l + 1) * NHEADS + h];
                sDtt[nxt] = d;
                sDec[nxt] = expf(d * A);
            }
        }
        float xp = sX[cur][p];
        float dtx = sDtt[cur] * xp;
        float dec = sDec[cur];
        float acc = 0.0f;
#pragma unroll
        for (int j = 0; j < 32; j++) {
            int n = q + 4 * j;
            float bn = sB[cur][n];
            float cn = sC[cur][n];
            s[j] = s[j] * dec + dtx * bn;
            acc += s[j] * cn;
        }
        acc += __shfl_xor_sync(0xffffffffu, acc, 1);
        acc += __shfl_xor_sync(0xffffffffu, acc, 2);
        if (q == 0)
            y[(size_t)(b * L_ + l) * D_INNER + h * HEADDIM + p] = acc + Dh * xp;
        __syncthreads();
    }
}

// ---------------- gate (y * silu(z)) + RMSNorm ------------------------------
__global__ void gate_rms_kernel(const float* __restrict__ zx,
                                const float* __restrict__ rms_w,
                                float* __restrict__ y) {
    int tok = blockIdx.x;
    int t = threadIdx.x;  // 256, 4 elems each
    float v[4];
    float ss = 0.0f;
#pragma unroll
    for (int j = 0; j < 4; j++) {
        int c = t + j * 256;
        float z = zx[(size_t)tok * D_IN_PROJ + c];
        float yy = y[(size_t)tok * D_INNER + c];
        float g = z / (1.0f + expf(-z));
        v[j] = yy * g;
        ss += v[j] * v[j];
    }
    __shared__ float red[256];
    red[t] = ss;
    __syncthreads();
#pragma unroll
    for (int s = 128; s > 0; s >>= 1) {
        if (t < s) red[t] += red[t + s];
        __syncthreads();
    }
    float inv = rsqrtf(red[0] * (1.0f / D_INNER) + 1e-5f);
#pragma unroll
    for (int j = 0; j < 4; j++) {
        int c = t + j * 256;
        y[(size_t)tok * D_INNER + c] = v[j] * inv * rms_w[c];
    }
}

// ---------------- launch -----------------------------------------------------
extern "C" void kernel_launch(void* const* d_in, const int* in_sizes, int n_in,
                              void* d_out, int out_size) {
    const float* states        = (const float*)d_in[0];
    const float* input_proj_w  = (const float*)d_in[1];
    const float* input_proj_b  = (const float*)d_in[2];
    const float* ln_g          = (const float*)d_in[3];
    const float* ln_b          = (const float*)d_in[4];
    const float* in_proj_w     = (const float*)d_in[5];
    const float* conv_w        = (const float*)d_in[6];
    const float* conv_b        = (const float*)d_in[7];
    const float* dt_bias       = (const float*)d_in[8];
    const float* A_log         = (const float*)d_in[9];
    const float* D_param       = (const float*)d_in[10];
    const float* rms_w         = (const float*)d_in[11];
    const float* out_proj_w    = (const float*)d_in[12];
    const float* post_ln_g     = (const float*)d_in[13];
    const float* post_ln_b     = (const float*)d_in[14];
    const float* output_proj_w = (const float*)d_in[15];
    const float* output_proj_b = (const float*)d_in[16];

    float *px, *ph, *pzx, *pxbc, *pdt, *py;
    cudaGetSymbolAddress((void**)&px, g_x);
    cudaGetSymbolAddress((void**)&ph, g_h);
    cudaGetSymbolAddress((void**)&pzx, g_zx);
    cudaGetSymbolAddress((void**)&pxbc, g_xbc);
    cudaGetSymbolAddress((void**)&pdt, g_dt);
    cudaGetSymbolAddress((void**)&py, g_y);

    input_rope_kernel<<<NTOK, 256>>>(states, input_proj_w, input_proj_b, px);

    for (int l = 0; l < N_LAYERS; l++) {
        layernorm_kernel<<<NTOK, 256>>>(px, ln_g + l * D_MODEL, ln_b + l * D_MODEL, ph);

        dim3 g1((D_IN_PROJ + BN - 1) / BN, NTOK / BM);
        tf32_gemm_kernel<<<g1, 256>>>(ph, in_proj_w + (size_t)l * D_MODEL * D_IN_PROJ,
                                      nullptr, nullptr, pzx, NTOK, D_IN_PROJ, D_MODEL);

        conv_silu_kernel<<<NTOK, 256>>>(pzx, conv_w + (size_t)l * CONV_DIM * D_CONV,
                                        conv_b + (size_t)l * CONV_DIM, pxbc);
        dt_kernel<<<(NTOK * NHEADS + 255) / 256, 256>>>(pzx, dt_bias + l * NHEADS, pdt);

        scan_kernel<<<dim3(NHEADS, B_), 256>>>(pxbc, pdt, A_log + l * NHEADS,
                                               D_param + l * NHEADS, py);

        gate_rms_kernel<<<NTOK, 256>>>(pzx, rms_w + (size_t)l * D_INNER, py);

        dim3 g2((D_MODEL + BN - 1) / BN, NTOK / BM);
        tf32_gemm_kernel<<<g2, 256>>>(py, out_proj_w + (size_t)l * D_INNER * D_MODEL,
                                      nullptr, px, px, NTOK, D_MODEL, D_INNER);
    }

    layernorm_kernel<<<NTOK, 256>>>(px, post_ln_g, post_ln_b, ph);
    dim3 g3((D_MODEL + BN - 1) / BN, NTOK / BM);
    tf32_gemm_kernel<<<g3, 256>>>(ph, output_proj_w, output_proj_b, nullptr,
                                  (float*)d_out, NTOK, D_MODEL, D_MODEL);
}

// round 12
// speedup vs baseline: 1.5622x; 1.5431x over previous
#include <cuda_runtime.h>
#include <cuda_bf16.h>
#include <math.h>
#include <stdint.h>

#define B_ 16
#define L_ 1024
#define STATE_DIM 17
#define D_MODEL 512
#define D_STATE 128
#define D_CONV 4
#define N_LAYERS 6
#define HEADDIM 64
#define D_INNER 1024
#define NHEADS 16
#define CONV_DIM 1280          // D_INNER + 2*D_STATE
#define D_IN_PROJ 2320         // 2*D_INNER + 2*D_STATE + NHEADS
#define NTOK (B_*L_)

// ---------------- scratch (allocation-free: __device__ globals) -------------
__device__ float g_x[NTOK * D_MODEL];        // residual stream
__device__ float g_zx[NTOK * D_IN_PROJ];     // in_proj output
__device__ float g_xbc[NTOK * CONV_DIM];     // conv+silu output
__device__ float g_dt[NTOK * NHEADS];        // softplus(dt + bias)
__device__ float g_y[NTOK * D_INNER];        // scan output
// split-bf16 activations (GEMM A operands)
__device__ __nv_bfloat16 g_hh[NTOK * D_MODEL];   // layernorm out hi
__device__ __nv_bfloat16 g_hl[NTOK * D_MODEL];   // layernorm out lo
__device__ __nv_bfloat16 g_yh[NTOK * D_INNER];   // gated+rms out hi
__device__ __nv_bfloat16 g_yl[NTOK * D_INNER];   // gated+rms out lo
// split-bf16 transposed weights [N][K] (hi/lo)
__device__ __nv_bfloat16 g_wih[N_LAYERS * D_IN_PROJ * D_MODEL];
__device__ __nv_bfloat16 g_wil[N_LAYERS * D_IN_PROJ * D_MODEL];
__device__ __nv_bfloat16 g_woh[N_LAYERS * D_MODEL * D_INNER];
__device__ __nv_bfloat16 g_wol[N_LAYERS * D_MODEL * D_INNER];
__device__ __nv_bfloat16 g_wfh[D_MODEL * D_MODEL];
__device__ __nv_bfloat16 g_wfl[D_MODEL * D_MODEL];

// ---------------- PTX helpers (plain sm_103-safe: no 'a' features) ----------
__device__ __forceinline__ uint32_t smem_to_u32(const void* smem_ptr) {
    uint32_t addr;
    asm("{ .reg .u64 tmp; cvta.to.shared.u64 tmp, %1; cvt.u32.u64 %0, tmp; }"
        : "=r"(addr) : "l"(smem_ptr));
    return addr;
}
#define CP_ASYNC16(dst, src) \
    asm volatile("cp.async.cg.shared.global [%0], [%1], 16;" \
                 :: "r"(dst), "l"(src) : "memory")
#define CP_COMMIT() asm volatile("cp.async.commit_group;" ::: "memory")
#define CP_WAIT1() asm volatile("cp.async.wait_group 1;" ::: "memory")
#define CP_WAIT0() asm volatile("cp.async.wait_group 0;" ::: "memory")
#define LDMX4(r, addr) \
    asm volatile("ldmatrix.sync.aligned.m8n8.x4.shared.b16 {%0,%1,%2,%3}, [%4];" \
                 : "=r"((r)[0]), "=r"((r)[1]), "=r"((r)[2]), "=r"((r)[3]) \
                 : "r"(addr))
#define MMA_BF16(c, a, b) \
    asm volatile("mma.sync.aligned.m16n8k16.row.col.f32.bf16.bf16.f32 " \
                 "{%0,%1,%2,%3}, {%4,%5,%6,%7}, {%8,%9}, {%0,%1,%2,%3};" \
                 : "+f"((c)[0]), "+f"((c)[1]), "+f"((c)[2]), "+f"((c)[3]) \
                 : "r"((a)[0]), "r"((a)[1]), "r"((a)[2]), "r"((a)[3]), \
                   "r"((b)[0]), "r"((b)[1]))

// ---------------- input projection + RoPE ----------------------------------
__global__ void input_rope_kernel(const float* __restrict__ states,
                                  const float* __restrict__ W,
                                  const float* __restrict__ bias,
                                  float* __restrict__ out) {
    int tok = blockIdx.x;
    int l = tok % L_;
    __shared__ float s[STATE_DIM];
    int t = threadIdx.x;  // 256 threads = 256 rope pairs
    if (t < STATE_DIM) s[t] = states[tok * STATE_DIM + t];
    __syncthreads();
    float x1 = bias[2 * t], x2 = bias[2 * t + 1];
#pragma unroll
    for (int k = 0; k < STATE_DIM; k++) {
        float sv = s[k];
        x1 += sv * W[k * D_MODEL + 2 * t];
        x2 += sv * W[k * D_MODEL + 2 * t + 1];
    }
    float inv = expf(-((2.0f * t) / (float)D_MODEL) * logf(10000.0f));
    float fr = (float)l * inv;
    float c = cosf(fr), sn = sinf(fr);
    out[tok * D_MODEL + 2 * t]     = x1 * c - x2 * sn;
    out[tok * D_MODEL + 2 * t + 1] = x1 * sn + x2 * c;
}

// ---------------- layernorm -> split bf16 (D_MODEL=512) ---------------------
__global__ void layernorm_split_kernel(const float* __restrict__ x,
                                       const float* __restrict__ g,
                                       const float* __restrict__ b,
                                       __nv_bfloat16* __restrict__ oh,
                                       __nv_bfloat16* __restrict__ ol) {
    int tok = blockIdx.x;
    int t = threadIdx.x;  // 256
    float v0 = x[tok * D_MODEL + t];
    float v1 = x[tok * D_MODEL + 256 + t];
    __shared__ float red[256];
    red[t] = v0 + v1;
    __syncthreads();
#pragma unroll
    for (int s = 128; s > 0; s >>= 1) {
        if (t < s) red[t] += red[t + s];
        __syncthreads();
    }
    float mu = red[0] * (1.0f / D_MODEL);
    __syncthreads();
    float c0 = v0 - mu, c1 = v1 - mu;
    red[t] = c0 * c0 + c1 * c1;
    __syncthreads();
#pragma unroll
    for (int s = 128; s > 0; s >>= 1) {
        if (t < s) red[t] += red[t + s];
        __syncthreads();
    }
    float inv = rsqrtf(red[0] * (1.0f / D_MODEL) + 1e-5f);
    float o0 = c0 * inv * g[t] + b[t];
    float o1 = c1 * inv * g[256 + t] + b[256 + t];
    __nv_bfloat16 h0 = __float2bfloat16(o0);
    __nv_bfloat16 h1 = __float2bfloat16(o1);
    oh[tok * D_MODEL + t]       = h0;
    oh[tok * D_MODEL + 256 + t] = h1;
    ol[tok * D_MODEL + t]       = __float2bfloat16(o0 - __bfloat162float(h0));
    ol[tok * D_MODEL + 256 + t] = __float2bfloat16(o1 - __bfloat162float(h1));
}

// ---------------- fp32 layernorm (kept for nothing but clarity removed) -----

// ---------------- weight transpose + bf16 hi/lo split -----------------------
// W[K][N] fp32 (row-major) -> Th[N][K], Tl[N][K] bf16. K % 32 == 0.
__global__ void transpose_split_kernel(const float* __restrict__ W,
                                       __nv_bfloat16* __restrict__ Th,
                                       __nv_bfloat16* __restrict__ Tl,
                                       int K, int N) {
    __shared__ float tile[32][33];
    int k0 = blockIdx.x * 32, n0 = blockIdx.y * 32;
    int tx = threadIdx.x, ty = threadIdx.y;  // 32 x 8
#pragma unroll
    for (int r = ty; r < 32; r += 8) {
        int n = n0 + tx;
        tile[r][tx] = (n < N) ? W[(size_t)(k0 + r) * N + n] : 0.0f;
    }
    __syncthreads();
#pragma unroll
    for (int r = ty; r < 32; r += 8) {
        int n = n0 + r, k = k0 + tx;
        if (n < N) {
            float v = tile[tx][r];
            __nv_bfloat16 h = __float2bfloat16(v);
            __nv_bfloat16 l = __float2bfloat16(v - __bfloat162float(h));
            Th[(size_t)n * K + k] = h;
            Tl[(size_t)n * K + k] = l;
        }
    }
}

// ---------------- split-bf16 HMMA GEMM ---------------------------------------
// C[M,N] = A @ B^T (+bias)(+res). A: [M][K] bf16 hi/lo; B: [N][K] bf16 hi/lo.
// 3-term: ah*bh + ah*bl + al*bh, fp32 accum. CTA tile 128x128, BK=32,
// 256 thr = 8 warps (2x4), warp tile 64x32, mma.m16n8k16, ldmatrix.x4,
// cp.async double-buffered. M%128==0, K%32==0, N even.
#define GKC 32
#define ROWB 80                 // bytes per smem row (64 data + 16 pad)
#define OFF_AH 0
#define OFF_AL 10240
#define OFF_BH 20480
#define OFF_BL 30720
#define STG_BYTES 40960
#define GEMM_SMEM (2 * STG_BYTES)

__device__ __forceinline__ void gemm_fill(
    uint32_t sa, int tid,
    const __nv_bfloat16* __restrict__ Ah, const __nv_bfloat16* __restrict__ Al,
    const __nv_bfloat16* __restrict__ Bh, const __nv_bfloat16* __restrict__ Bl,
    int m0, int n0, int N, int K, int k0) {
#pragma unroll
    for (int c = tid; c < 512; c += 256) {
        int row = c >> 2, q = c & 3;
        uint32_t d = sa + row * ROWB + q * 16;
        size_t aoff = (size_t)(m0 + row) * K + k0 + q * 8;
        CP_ASYNC16(d + OFF_AH, Ah + aoff);
        CP_ASYNC16(d + OFF_AL, Al + aoff);
        int nr = n0 + row; if (nr >= N) nr = N - 1;   // clamp: cols >= N unused
        size_t boff = (size_t)nr * K + k0 + q * 8;
        CP_ASYNC16(d + OFF_BH, Bh + boff);
        CP_ASYNC16(d + OFF_BL, Bl + boff);
    }
    CP_COMMIT();
}

__global__ __launch_bounds__(256) void hmma_gemm_kernel(
    const __nv_bfloat16* __restrict__ Ah, const __nv_bfloat16* __restrict__ Al,
    const __nv_bfloat16* __restrict__ Bh, const __nv_bfloat16* __restrict__ Bl,
    const float* __restrict__ bias, const float* __restrict__ res,
    float* __restrict__ C, int M, int N, int K) {
    extern __shared__ char smem[];
    uint32_t sb = smem_to_u32(smem);
    int tid = threadIdx.x;
    int warp = tid >> 5, lane = tid & 31;
    int grp = lane >> 2, qid = lane & 3;
    int wm = (warp >> 2) * 64;
    int wn = (warp & 3) * 32;
    int brow = blockIdx.y, bcol = blockIdx.x;
    int m0 = brow * 128, n0 = bcol * 128;

    float acc[4][4][4];
#pragma unroll
    for (int i = 0; i < 4; i++)
#pragma unroll
        for (int j = 0; j < 4; j++)
#pragma unroll
            for (int r = 0; r < 4; r++) acc[i][j][r] = 0.0f;

    // ldmatrix lane addressing
    int lr = lane & 7;
    int arow = ((lane >> 3) & 1) * 8;      // A: lanes 8-15/24-31 -> rows +8
    int acol = (lane >> 4) * 16;           // A: lanes 16-31 -> k +8 (16B)
    int brw  = (lane >> 4) * 8;            // B: lanes 16-31 -> n rows +8
    int bcl  = ((lane >> 3) & 1) * 16;     // B: lanes 8-15/24-31 -> k +8

    int nch = K / GKC;
    gemm_fill(sb, tid, Ah, Al, Bh, Bl, m0, n0, N, K, 0);

    for (int ch = 0; ch < nch; ch++) {
        if (ch + 1 < nch) {
            gemm_fill(sb + ((ch + 1) & 1) * STG_BYTES, tid,
                      Ah, Al, Bh, Bl, m0, n0, N, K, (ch + 1) * GKC);
            CP_WAIT1();
        } else {
            CP_WAIT0();
        }
        __syncthreads();
        uint32_t sa = sb + (ch & 1) * STG_BYTES;
#pragma unroll
        for (int ks = 0; ks < 2; ks++) {
            int kb = ks * 32;  // bytes: 16 bf16 per k-step
            uint32_t ah[4][4], al[4][4];
#pragma unroll
            for (int mi = 0; mi < 4; mi++) {
                uint32_t r = sa + OFF_AH +
                    (uint32_t)((wm + mi * 16 + lr + arow) * ROWB + kb + acol);
                LDMX4(ah[mi], r);
                LDMX4(al[mi], r + (OFF_AL - OFF_AH));
            }
            uint32_t bh[4][2], bl[4][2];
#pragma unroll
            for (int nb = 0; nb < 2; nb++) {
                uint32_t r = sa + OFF_BH +
                    (uint32_t)((wn + nb * 16 + lr + brw) * ROWB + kb + bcl);
                uint32_t tb[4];
                LDMX4(tb, r);
                bh[2 * nb][0] = tb[0]; bh[2 * nb][1] = tb[1];
                bh[2 * nb + 1][0] = tb[2]; bh[2 * nb + 1][1] = tb[3];
                LDMX4(tb, r + (OFF_BL - OFF_BH));
                bl[2 * nb][0] = tb[0]; bl[2 * nb][1] = tb[1];
                bl[2 * nb + 1][0] = tb[2]; bl[2 * nb + 1][1] = tb[3];
            }
#pragma unroll
            for (int mi = 0; mi < 4; mi++)
#pragma unroll
                for (int ni = 0; ni < 4; ni++) {
                    MMA_BF16(acc[mi][ni], ah[mi], bh[ni]);
                    MMA_BF16(acc[mi][ni], ah[mi], bl[ni]);
                    MMA_BF16(acc[mi][ni], al[mi], bh[ni]);
                }
        }
        __syncthreads();
    }

    // ---- epilogue ----
#pragma unroll
    for (int mi = 0; mi < 4; mi++) {
#pragma unroll
        for (int half = 0; half < 2; half++) {
            int grow = m0 + wm + mi * 16 + grp + half * 8;
#pragma unroll
            for (int ni = 0; ni < 4; ni++) {
                int gcol = n0 + wn + ni * 8 + qid * 2;
                if (gcol < N) {   // N even -> pair in-bounds together
                    float v0 = acc[mi][ni][half * 2 + 0];
                    float v1 = acc[mi][ni][half * 2 + 1];
                    if (bias) { v0 += bias[gcol]; v1 += bias[gcol + 1]; }
                    if (res) {
                        const float* rp = res + (size_t)grow * N + gcol;
                        v0 += rp[0]; v1 += rp[1];
                    }
                    *(float2*)(C + (size_t)grow * N + gcol) = make_float2(v0, v1);
                }
            }
        }
    }
}

// ---------------- causal conv1d (K=4, depthwise) + SiLU ---------------------
__global__ void conv_silu_kernel(const float* __restrict__ zx,
                                 const float* __restrict__ cw,
                                 const float* __restrict__ cb,
                                 float* __restrict__ xbc) {
    int tok = blockIdx.x;
    int b = tok / L_;
    int l = tok % L_;
    for (int c = threadIdx.x; c < CONV_DIM; c += 256) {
        float acc = cb[c];
        float w0 = cw[c * D_CONV + 0], w1 = cw[c * D_CONV + 1];
        float w2 = cw[c * D_CONV + 2], w3 = cw[c * D_CONV + 3];
        const float* base = zx + (size_t)(b * L_) * D_IN_PROJ + D_INNER + c;
        if (l >= 3) acc += base[(size_t)(l - 3) * D_IN_PROJ] * w0;
        if (l >= 2) acc += base[(size_t)(l - 2) * D_IN_PROJ] * w1;
        if (l >= 1) acc += base[(size_t)(l - 1) * D_IN_PROJ] * w2;
        acc += base[(size_t)l * D_IN_PROJ] * w3;
        xbc[(size_t)tok * CONV_DIM + c] = acc / (1.0f + expf(-acc));
    }
}

// ---------------- dt = softplus(dt_raw + bias) ------------------------------
__global__ void dt_kernel(const float* __restrict__ zx,
                          const float* __restrict__ dt_bias,
                          float* __restrict__ dto) {
    int i = blockIdx.x * blockDim.x + threadIdx.x;
    if (i >= NTOK * NHEADS) return;
    int h = i % NHEADS;
    int tok = i / NHEADS;
    float v = zx[(size_t)tok * D_IN_PROJ + D_INNER + CONV_DIM + h] + dt_bias[h];
    dto[i] = (v > 20.0f) ? v : log1pf(expf(v));
}

// ---------------- selective scan (sequential over L) ------------------------
// grid = (NHEADS, B_), block = 256. Thread t: p = t>>2, q = t&3; owns
// contiguous n in [q*32, q*32+32) -> vectorized LDS.128 from padded rows.
__global__ __launch_bounds__(256) void scan_kernel(
    const float* __restrict__ xbc, const float* __restrict__ dt,
    const float* __restrict__ A_log, const float* __restrict__ Dp,
    float* __restrict__ y) {
    int h = blockIdx.x, b = blockIdx.y;
    int t = threadIdx.x;
    int p = t >> 2;
    int q = t & 3;
    __shared__ float sB[2][144], sC[2][144], sX[2][HEADDIM];
    __shared__ float sDec[2], sDtt[2];
    float A = -expf(A_log[h]);
    float Dh = Dp[h];
    float s[32];
#pragma unroll
    for (int j = 0; j < 32; j++) s[j] = 0.0f;

    {
        const float* base = xbc + (size_t)(b * L_) * CONV_DIM;
        if (t < 128) {
            int idx = (t >> 5) * 36 + (t & 31);
            sB[0][idx] = base[D_INNER + t];
            sC[0][idx] = base[D_INNER + D_STATE + t];
        } else if (t < 192) {
            sX[0][t - 128] = base[h * HEADDIM + (t - 128)];
        } else if (t == 255) {
            float d = dt[(size_t)(b * L_) * NHEADS + h];
            sDtt[0] = d;
            sDec[0] = expf(d * A);
        }
    }
    __syncthreads();

    int q36 = q * 36;
    for (int l = 0; l < L_; l++) {
        int cur = l & 1, nxt = cur ^ 1;
        if (l + 1 < L_) {
            const float* base = xbc + (size_t)(b * L_ + l + 1) * CONV_DIM;
            if (t < 128) {
                int idx = (t >> 5) * 36 + (t & 31);
                sB[nxt][idx] = base[D_INNER + t];
                sC[nxt][idx] = base[D_INNER + D_STATE + t];
            } else if (t < 192) {
                sX[nxt][t - 128] = base[h * HEADDIM + (t - 128)];
            } else if (t == 255) {
                float d = dt[(size_t)(b * L_ + l + 1) * NHEADS + h];
                sDtt[nxt] = d;
                sDec[nxt] = expf(d * A);
            }
        }
        float xp = sX[cur][p];
        float dtx = sDtt[cur] * xp;
        float dec = sDec[cur];
        float acc0 = 0.0f, acc1 = 0.0f;
#pragma unroll
        for (int jj = 0; jj < 8; jj++) {
            float4 b4 = *(const float4*)&sB[cur][q36 + jj * 4];
            float4 c4 = *(const float4*)&sC[cur][q36 + jj * 4];
            int j = jj * 4;
            s[j + 0] = s[j + 0] * dec + dtx * b4.x;  acc0 += s[j + 0] * c4.x;
            s[j + 1] = s[j + 1] * dec + dtx * b4.y;  acc1 += s[j + 1] * c4.y;
            s[j + 2] = s[j + 2] * dec + dtx * b4.z;  acc0 += s[j + 2] * c4.z;
            s[j + 3] = s[j + 3] * dec + dtx * b4.w;  acc1 += s[j + 3] * c4.w;
        }
        float acc = acc0 + acc1;
        acc += __shfl_xor_sync(0xffffffffu, acc, 1);
        acc += __shfl_xor_sync(0xffffffffu, acc, 2);
        if (q == 0)
            y[(size_t)(b * L_ + l) * D_INNER + h * HEADDIM + p] = acc + Dh * xp;
        __syncthreads();
    }
}

// ---------------- gate (y * silu(z)) + RMSNorm -> split bf16 -----------------
__global__ void gate_rms_split_kernel(const float* __restrict__ zx,
                                      const float* __restrict__ rms_w,
                                      const float* __restrict__ y,
                                      __nv_bfloat16* __restrict__ oh,
                                      __nv_bfloat16* __restrict__ ol) {
    int tok = blockIdx.x;
    int t = threadIdx.x;  // 256, 4 elems each
    float v[4];
    float ss = 0.0f;
#pragma unroll
    for (int j = 0; j < 4; j++) {
        int c = t + j * 256;
        float z = zx[(size_t)tok * D_IN_PROJ + c];
        float yy = y[(size_t)tok * D_INNER + c];
        float g = z / (1.0f + expf(-z));
        v[j] = yy * g;
        ss += v[j] * v[j];
    }
    __shared__ float red[256];
    red[t] = ss;
    __syncthreads();
#pragma unroll
    for (int s = 128; s > 0; s >>= 1) {
        if (t < s) red[t] += red[t + s];
        __syncthreads();
    }
    float inv = rsqrtf(red[0] * (1.0f / D_INNER) + 1e-5f);
#pragma unroll
    for (int j = 0; j < 4; j++) {
        int c = t + j * 256;
        float o = v[j] * inv * rms_w[c];
        __nv_bfloat16 hh = __float2bfloat16(o);
        oh[(size_t)tok * D_INNER + c] = hh;
        ol[(size_t)tok * D_INNER + c] = __float2bfloat16(o - __bfloat162float(hh));
    }
}

// ---------------- launch -----------------------------------------------------
extern "C" void kernel_launch(void* const* d_in, const int* in_sizes, int n_in,
                              void* d_out, int out_size) {
    const float* states        = (const float*)d_in[0];
    const float* input_proj_w  = (const float*)d_in[1];
    const float* input_proj_b  = (const float*)d_in[2];
    const float* ln_g          = (const float*)d_in[3];
    const float* ln_b          = (const float*)d_in[4];
    const float* in_proj_w     = (const float*)d_in[5];
    const float* conv_w        = (const float*)d_in[6];
    const float* conv_b        = (const float*)d_in[7];
    const float* dt_bias       = (const float*)d_in[8];
    const float* A_log         = (const float*)d_in[9];
    const float* D_param       = (const float*)d_in[10];
    const float* rms_w         = (const float*)d_in[11];
    const float* out_proj_w    = (const float*)d_in[12];
    const float* post_ln_g     = (const float*)d_in[13];
    const float* post_ln_b     = (const float*)d_in[14];
    const float* output_proj_w = (const float*)d_in[15];
    const float* output_proj_b = (const float*)d_in[16];

    float *px, *pzx, *pxbc, *pdt, *py;
    cudaGetSymbolAddress((void**)&px, g_x);
    cudaGetSymbolAddress((void**)&pzx, g_zx);
    cudaGetSymbolAddress((void**)&pxbc, g_xbc);
    cudaGetSymbolAddress((void**)&pdt, g_dt);
    cudaGetSymbolAddress((void**)&py, g_y);
    __nv_bfloat16 *phh, *phl, *pyh, *pyl;
    cudaGetSymbolAddress((void**)&phh, g_hh);
    cudaGetSymbolAddress((void**)&phl, g_hl);
    cudaGetSymbolAddress((void**)&pyh, g_yh);
    cudaGetSymbolAddress((void**)&pyl, g_yl);
    __nv_bfloat16 *pwih, *pwil, *pwoh, *pwol, *pwfh, *pwfl;
    cudaGetSymbolAddress((void**)&pwih, g_wih);
    cudaGetSymbolAddress((void**)&pwil, g_wil);
    cudaGetSymbolAddress((void**)&pwoh, g_woh);
    cudaGetSymbolAddress((void**)&pwol, g_wol);
    cudaGetSymbolAddress((void**)&pwfh, g_wfh);
    cudaGetSymbolAddress((void**)&pwfl, g_wfl);

    cudaFuncSetAttribute(hmma_gemm_kernel,
                         cudaFuncAttributeMaxDynamicSharedMemorySize, GEMM_SMEM);

    // ---- pre-split weights (inside the graph; deterministic) ----
    dim3 tb(32, 8);
    for (int l = 0; l < N_LAYERS; l++) {
        transpose_split_kernel<<<dim3(D_MODEL / 32, (D_IN_PROJ + 31) / 32), tb>>>(
            in_proj_w + (size_t)l * D_MODEL * D_IN_PROJ,
            pwih + (size_t)l * D_IN_PROJ * D_MODEL,
            pwil + (size_t)l * D_IN_PROJ * D_MODEL, D_MODEL, D_IN_PROJ);
        transpose_split_kernel<<<dim3(D_INNER / 32, D_MODEL / 32), tb>>>(
            out_proj_w + (size_t)l * D_INNER * D_MODEL,
            pwoh + (size_t)l * D_MODEL * D_INNER,
            pwol + (size_t)l * D_MODEL * D_INNER, D_INNER, D_MODEL);
    }
    transpose_split_kernel<<<dim3(D_MODEL / 32, D_MODEL / 32), tb>>>(
        output_proj_w, pwfh, pwfl, D_MODEL, D_MODEL);

    input_rope_kernel<<<NTOK, 256>>>(states, input_proj_w, input_proj_b, px);

    for (int l = 0; l < N_LAYERS; l++) {
        layernorm_split_kernel<<<NTOK, 256>>>(px, ln_g + l * D_MODEL,
                                              ln_b + l * D_MODEL, phh, phl);

        dim3 g1((D_IN_PROJ + 127) / 128, NTOK / 128);
        hmma_gemm_kernel<<<g1, 256, GEMM_SMEM>>>(
            phh, phl,
            pwih + (size_t)l * D_IN_PROJ * D_MODEL,
            pwil + (size_t)l * D_IN_PROJ * D_MODEL,
            nullptr, nullptr, pzx, NTOK, D_IN_PROJ, D_MODEL);

        conv_silu_kernel<<<NTOK, 256>>>(pzx, conv_w + (size_t)l * CONV_DIM * D_CONV,
                                        conv_b + (size_t)l * CONV_DIM, pxbc);
        dt_kernel<<<(NTOK * NHEADS + 255) / 256, 256>>>(pzx, dt_bias + l * NHEADS, pdt);

        scan_kernel<<<dim3(NHEADS, B_), 256>>>(pxbc, pdt, A_log + l * NHEADS,
                                               D_param + l * NHEADS, py);

        gate_rms_split_kernel<<<NTOK, 256>>>(pzx, rms_w + (size_t)l * D_INNER,
                                             py, pyh, pyl);

        dim3 g2(D_MODEL / 128, NTOK / 128);
        hmma_gemm_kernel<<<g2, 256, GEMM_SMEM>>>(
            pyh, pyl,
            pwoh + (size_t)l * D_MODEL * D_INNER,
            pwol + (size_t)l * D_MODEL * D_INNER,
            nullptr, px, px, NTOK, D_MODEL, D_INNER);
    }

    layernorm_split_kernel<<<NTOK, 256>>>(px, post_ln_g, post_ln_b, phh, phl);
    dim3 g3(D_MODEL / 128, NTOK / 128);
    hmma_gemm_kernel<<<g3, 256, GEMM_SMEM>>>(
        phh, phl, pwfh, pwfl, output_proj_b, nullptr,
        (float*)d_out, NTOK, D_MODEL, D_MODEL);
}